// round 1
// baseline (speedup 1.0000x reference)
#include <cuda_runtime.h>

// Fused 2-layer LSTM + time-softmax(last) + 3-layer dense head + softmax.
// One warp per batch element. Lane j owns gate rows j (i/f) and j+32 (g/o).
// Packed f32x2 FMAs over k-pairs. h state broadcast via per-warp smem
// (double-buffered), merged i/g vs f/o halves via shfl_down by 16.

#define FULLMASK 0xffffffffu
#define LOG2E 1.4426950408889634f

static __device__ __forceinline__ unsigned long long ffma2(
    unsigned long long a, unsigned long long b, unsigned long long c) {
    unsigned long long d;
    asm("fma.rn.f32x2 %0, %1, %2, %3;" : "=l"(d) : "l"(a), "l"(b), "l"(c));
    return d;
}
static __device__ __forceinline__ unsigned long long pack2(float lo, float hi) {
    unsigned long long d;
    asm("mov.b64 %0, {%1, %2};" : "=l"(d) : "f"(lo), "f"(hi));
    return d;
}
static __device__ __forceinline__ float2 unpack2(unsigned long long v) {
    float lo, hi;
    asm("mov.b64 {%0, %1}, %2;" : "=f"(lo), "=f"(hi) : "l"(v));
    return make_float2(lo, hi);
}
static __device__ __forceinline__ float ex2f(float x) {
    float y; asm("ex2.approx.f32 %0, %1;" : "=f"(y) : "f"(x)); return y;
}
static __device__ __forceinline__ float rcpf(float x) {
    float y; asm("rcp.approx.f32 %0, %1;" : "=f"(y) : "f"(x)); return y;
}

__global__ void __launch_bounds__(128, 3)
lstm_fused_kernel(const float* __restrict__ x,
                  const float* __restrict__ Wih1, const float* __restrict__ Whh1,
                  const float* __restrict__ bih1, const float* __restrict__ bhh1,
                  const float* __restrict__ Wih2, const float* __restrict__ Whh2,
                  const float* __restrict__ bih2, const float* __restrict__ bhh2,
                  const float* __restrict__ Wd1, const float* __restrict__ bd1,
                  const float* __restrict__ Wd2, const float* __restrict__ bd2,
                  const float* __restrict__ Wd3, const float* __restrict__ bd3,
                  float* __restrict__ out)
{
    constexpr int T = 512, IN = 11;
    const int lane = threadIdx.x & 31;
    const int wid  = threadIdx.x >> 5;
    const int b    = blockIdx.x * 4 + wid;

    __shared__ __align__(16) float sh1[4][2][16];
    __shared__ __align__(16) float sh2[4][2][16];

    const int j = lane, jh = lane + 32;

    // ---- packed weights (pairs along k) ----
    unsigned long long wi1L[6], wi1H[6];
#pragma unroll
    for (int k = 0; k < 6; ++k) {
        const int c0 = 2 * k, c1 = 2 * k + 1;
        float lv = (c1 < IN) ? Wih1[j * IN + c1] : 0.f;
        float hv = (c1 < IN) ? Wih1[jh * IN + c1] : 0.f;
        wi1L[k] = pack2(Wih1[j * IN + c0], lv);
        wi1H[k] = pack2(Wih1[jh * IN + c0], hv);
    }
    unsigned long long wh1L[8], wh1H[8], wi2L[8], wi2H[8], wh2L[8], wh2H[8];
#pragma unroll
    for (int k = 0; k < 8; ++k) {
        wh1L[k] = pack2(Whh1[j  * 16 + 2 * k], Whh1[j  * 16 + 2 * k + 1]);
        wh1H[k] = pack2(Whh1[jh * 16 + 2 * k], Whh1[jh * 16 + 2 * k + 1]);
        wi2L[k] = pack2(Wih2[j  * 16 + 2 * k], Wih2[j  * 16 + 2 * k + 1]);
        wi2H[k] = pack2(Wih2[jh * 16 + 2 * k], Wih2[jh * 16 + 2 * k + 1]);
        wh2L[k] = pack2(Whh2[j  * 16 + 2 * k], Whh2[j  * 16 + 2 * k + 1]);
        wh2H[k] = pack2(Whh2[jh * 16 + 2 * k], Whh2[jh * 16 + 2 * k + 1]);
    }
    const unsigned long long b1L = pack2(bih1[j]  + bhh1[j],  0.f);
    const unsigned long long b1H = pack2(bih1[jh] + bhh1[jh], 0.f);
    const unsigned long long b2L = pack2(bih2[j]  + bhh2[j],  0.f);
    const unsigned long long b2H = pack2(bih2[jh] + bhh2[jh], 0.f);

    // hi-gate activation: tanh for lanes<16 (g gate), sigmoid for lanes>=16 (o gate)
    const bool hiT = (lane < 16);
    const float cm = hiT ? (-2.f * LOG2E) : (-LOG2E);
    const float cA = hiT ? 2.f : 1.f;
    const float cB = hiT ? -1.f : 0.f;

    if (lane < 16) { sh1[wid][0][lane] = 0.f; sh2[wid][0][lane] = 0.f; }
    __syncwarp();

    const float* xp = x + (size_t)b * (T * IN);
    float cc1 = 0.f, cc2 = 0.f, h2 = 0.f, ssum = 0.f;

    for (int t = 0; t < T; ++t) {
        const int rp = t & 1, wp = rp ^ 1;

        // x pairs (warp-uniform broadcast loads)
        unsigned long long xq0 = pack2(__ldg(xp + 0), __ldg(xp + 1));
        unsigned long long xq1 = pack2(__ldg(xp + 2), __ldg(xp + 3));
        unsigned long long xq2 = pack2(__ldg(xp + 4), __ldg(xp + 5));
        unsigned long long xq3 = pack2(__ldg(xp + 6), __ldg(xp + 7));
        unsigned long long xq4 = pack2(__ldg(xp + 8), __ldg(xp + 9));
        unsigned long long xq5 = pack2(__ldg(xp + 10), 0.f);
        xp += IN;

        // ================= layer 1 =================
        unsigned long long aL = b1L, aH = b1H;
        {
            const ulonglong2* hp = (const ulonglong2*)(&sh1[wid][rp][0]);
            ulonglong2 p0 = hp[0], p1 = hp[1], p2 = hp[2], p3 = hp[3];
            aL = ffma2(wh1L[0], p0.x, aL); aH = ffma2(wh1H[0], p0.x, aH);
            aL = ffma2(wh1L[1], p0.y, aL); aH = ffma2(wh1H[1], p0.y, aH);
            aL = ffma2(wh1L[2], p1.x, aL); aH = ffma2(wh1H[2], p1.x, aH);
            aL = ffma2(wh1L[3], p1.y, aL); aH = ffma2(wh1H[3], p1.y, aH);
            aL = ffma2(wh1L[4], p2.x, aL); aH = ffma2(wh1H[4], p2.x, aH);
            aL = ffma2(wh1L[5], p2.y, aL); aH = ffma2(wh1H[5], p2.y, aH);
            aL = ffma2(wh1L[6], p3.x, aL); aH = ffma2(wh1H[6], p3.x, aH);
            aL = ffma2(wh1L[7], p3.y, aL); aH = ffma2(wh1H[7], p3.y, aH);
        }
        aL = ffma2(wi1L[0], xq0, aL); aH = ffma2(wi1H[0], xq0, aH);
        aL = ffma2(wi1L[1], xq1, aL); aH = ffma2(wi1H[1], xq1, aH);
        aL = ffma2(wi1L[2], xq2, aL); aH = ffma2(wi1H[2], xq2, aH);
        aL = ffma2(wi1L[3], xq3, aL); aH = ffma2(wi1H[3], xq3, aH);
        aL = ffma2(wi1L[4], xq4, aL); aH = ffma2(wi1H[4], xq4, aH);
        aL = ffma2(wi1L[5], xq5, aL); aH = ffma2(wi1H[5], xq5, aH);

        float2 vL = unpack2(aL), vH = unpack2(aH);
        float gLo = vL.x + vL.y, gHi = vH.x + vH.y;
        float actL = rcpf(1.f + ex2f(gLo * -LOG2E));                 // sigmoid (i or f)
        float actH = fmaf(cA, rcpf(1.f + ex2f(gHi * cm)), cB);      // tanh (g) / sigmoid (o)
        float fg = __shfl_down_sync(FULLMASK, actL, 16);
        float og = __shfl_down_sync(FULLMASK, actH, 16);
        cc1 = fmaf(fg, cc1, actL * actH);
        float th = fmaf(2.f, rcpf(1.f + ex2f(cc1 * (-2.f * LOG2E))), -1.f);
        float h1 = og * th;
        if (lane < 16) sh1[wid][wp][lane] = h1;
        __syncwarp();

        // ================= layer 2 =================
        unsigned long long aL2 = b2L, aH2 = b2H;
        {
            const ulonglong2* hp = (const ulonglong2*)(&sh1[wid][wp][0]);
            ulonglong2 p0 = hp[0], p1 = hp[1], p2 = hp[2], p3 = hp[3];
            aL2 = ffma2(wi2L[0], p0.x, aL2); aH2 = ffma2(wi2H[0], p0.x, aH2);
            aL2 = ffma2(wi2L[1], p0.y, aL2); aH2 = ffma2(wi2H[1], p0.y, aH2);
            aL2 = ffma2(wi2L[2], p1.x, aL2); aH2 = ffma2(wi2H[2], p1.x, aH2);
            aL2 = ffma2(wi2L[3], p1.y, aL2); aH2 = ffma2(wi2H[3], p1.y, aH2);
            aL2 = ffma2(wi2L[4], p2.x, aL2); aH2 = ffma2(wi2H[4], p2.x, aH2);
            aL2 = ffma2(wi2L[5], p2.y, aL2); aH2 = ffma2(wi2H[5], p2.y, aH2);
            aL2 = ffma2(wi2L[6], p3.x, aL2); aH2 = ffma2(wi2H[6], p3.x, aH2);
            aL2 = ffma2(wi2L[7], p3.y, aL2); aH2 = ffma2(wi2H[7], p3.y, aH2);
            const ulonglong2* qp = (const ulonglong2*)(&sh2[wid][rp][0]);
            ulonglong2 q0 = qp[0], q1 = qp[1], q2 = qp[2], q3 = qp[3];
            aL2 = ffma2(wh2L[0], q0.x, aL2); aH2 = ffma2(wh2H[0], q0.x, aH2);
            aL2 = ffma2(wh2L[1], q0.y, aL2); aH2 = ffma2(wh2H[1], q0.y, aH2);
            aL2 = ffma2(wh2L[2], q1.x, aL2); aH2 = ffma2(wh2H[2], q1.x, aH2);
            aL2 = ffma2(wh2L[3], q1.y, aL2); aH2 = ffma2(wh2H[3], q1.y, aH2);
            aL2 = ffma2(wh2L[4], q2.x, aL2); aH2 = ffma2(wh2H[4], q2.x, aH2);
            aL2 = ffma2(wh2L[5], q2.y, aL2); aH2 = ffma2(wh2H[5], q2.y, aH2);
            aL2 = ffma2(wh2L[6], q3.x, aL2); aH2 = ffma2(wh2H[6], q3.x, aH2);
            aL2 = ffma2(wh2L[7], q3.y, aL2); aH2 = ffma2(wh2H[7], q3.y, aH2);
        }
        vL = unpack2(aL2); vH = unpack2(aH2);
        gLo = vL.x + vL.y; gHi = vH.x + vH.y;
        actL = rcpf(1.f + ex2f(gLo * -LOG2E));
        actH = fmaf(cA, rcpf(1.f + ex2f(gHi * cm)), cB);
        fg = __shfl_down_sync(FULLMASK, actL, 16);
        og = __shfl_down_sync(FULLMASK, actH, 16);
        cc2 = fmaf(fg, cc2, actL * actH);
        th = fmaf(2.f, rcpf(1.f + ex2f(cc2 * (-2.f * LOG2E))), -1.f);
        h2 = og * th;
        if (lane < 16) sh2[wid][wp][lane] = h2;

        // time-softmax accumulation: h2 in (-1,1) => exp(h2) safe without max shift
        ssum += ex2f(h2 * LOG2E);
        __syncwarp();
    }

    // ---- epilogue: s = exp(h2_last)/sum_t exp(h2_t), then dense head ----
    float sval = ex2f(h2 * LOG2E) * rcpf(ssum);   // valid on lanes 0..15

    float d1 = bd1[j & 7];
#pragma unroll
    for (int k = 0; k < 16; ++k) {
        float sk = __shfl_sync(FULLMASK, sval, k);
        d1 = fmaf(Wd1[(j & 7) * 16 + k], sk, d1);
    }
    float d2 = bd2[j & 7];
#pragma unroll
    for (int k = 0; k < 8; ++k) {
        float dk = __shfl_sync(FULLMASK, d1, k);
        d2 = fmaf(Wd2[(j & 7) * 8 + k], dk, d2);
    }
    const int j3 = (lane < 3) ? lane : 0;
    float d3 = bd3[j3];
#pragma unroll
    for (int k = 0; k < 8; ++k) {
        float dk = __shfl_sync(FULLMASK, d2, k);
        d3 = fmaf(Wd3[j3 * 8 + k], dk, d3);
    }
    float v0 = __shfl_sync(FULLMASK, d3, 0);
    float v1 = __shfl_sync(FULLMASK, d3, 1);
    float v2 = __shfl_sync(FULLMASK, d3, 2);
    float m  = fmaxf(v0, fmaxf(v1, v2));
    float e0 = ex2f((v0 - m) * LOG2E);
    float e1 = ex2f((v1 - m) * LOG2E);
    float e2 = ex2f((v2 - m) * LOG2E);
    float inv = rcpf(e0 + e1 + e2);
    if (lane == 0) {
        out[b * 3 + 0] = e0 * inv;
        out[b * 3 + 1] = e1 * inv;
        out[b * 3 + 2] = e2 * inv;
    }
}

extern "C" void kernel_launch(void* const* d_in, const int* in_sizes, int n_in,
                              void* d_out, int out_size) {
    (void)in_sizes; (void)n_in; (void)out_size;
    const float* x    = (const float*)d_in[0];
    const float* Wih1 = (const float*)d_in[1];
    const float* Whh1 = (const float*)d_in[2];
    const float* bih1 = (const float*)d_in[3];
    const float* bhh1 = (const float*)d_in[4];
    const float* Wih2 = (const float*)d_in[5];
    const float* Whh2 = (const float*)d_in[6];
    const float* bih2 = (const float*)d_in[7];
    const float* bhh2 = (const float*)d_in[8];
    const float* Wd1  = (const float*)d_in[9];
    const float* bd1  = (const float*)d_in[10];
    const float* Wd2  = (const float*)d_in[11];
    const float* bd2  = (const float*)d_in[12];
    const float* Wd3  = (const float*)d_in[13];
    const float* bd3  = (const float*)d_in[14];
    float* out = (float*)d_out;

    // 4096 batch elems, 1 warp each, 4 warps per 128-thread block
    lstm_fused_kernel<<<1024, 128>>>(x, Wih1, Whh1, bih1, bhh1,
                                     Wih2, Whh2, bih2, bhh2,
                                     Wd1, bd1, Wd2, bd2, Wd3, bd3, out);
}